// round 9
// baseline (speedup 1.0000x reference)
#include <cuda_runtime.h>
#include <cuda_fp16.h>
#include <stdint.h>
#include <math.h>

#define TT 2048     // tokens
#define HH 2048     // hidden
#define FF 1408     // moe intermediate
#define EE 60       // experts
#define TK 4        // top-k
#define SS 5632     // shared intermediate
#define NP (TT*TK)  // routed pairs

// ---- fp16 operand buffers (converted once per call) ----
__device__ __align__(16) __half g_wgh[(size_t)EE*HH*FF];
__device__ __align__(16) __half g_wuh[(size_t)EE*HH*FF];
__device__ __align__(16) __half g_wdh[(size_t)EE*FF*HH];
__device__ __align__(16) __half g_shgh[(size_t)HH*SS];
__device__ __align__(16) __half g_shuh[(size_t)HH*SS];
__device__ __align__(16) __half g_shdh[(size_t)SS*HH];
__device__ __align__(16) __half g_xh[(size_t)TT*HH];
// ---- intermediates ----
__device__ __align__(16) __half g_ybuf16[(size_t)TT*SS];
__device__ __align__(16) __half g_hbuf16[(size_t)NP*FF];
__device__ float g_pbuf[(size_t)NP*HH];
// ---- routing ----
__device__ float g_topw[NP];
__device__ int   g_topidx[NP];
__device__ float g_sig[TT];
__device__ int   g_off[EE+1];
__device__ int   g_tok[NP];
__device__ int   g_pos[NP];

// ============================ helpers ============================
__device__ __forceinline__ uint32_t smem_u32(const void* p) {
    uint32_t a;
    asm("{ .reg .u64 t; cvta.to.shared.u64 t, %1; cvt.u32.u64 %0, t; }" : "=r"(a) : "l"(p));
    return a;
}
__device__ __forceinline__ void ldsm4(uint32_t r[4], uint32_t addr) {
    asm volatile("ldmatrix.sync.aligned.m8n8.x4.shared.b16 {%0,%1,%2,%3}, [%4];"
        : "=r"(r[0]), "=r"(r[1]), "=r"(r[2]), "=r"(r[3]) : "r"(addr));
}
__device__ __forceinline__ void ldsm4t(uint32_t r[4], uint32_t addr) {
    asm volatile("ldmatrix.sync.aligned.m8n8.x4.trans.shared.b16 {%0,%1,%2,%3}, [%4];"
        : "=r"(r[0]), "=r"(r[1]), "=r"(r[2]), "=r"(r[3]) : "r"(addr));
}
__device__ __forceinline__ void mma_f16(float c[4], const uint32_t a[4], uint32_t b0, uint32_t b1) {
    asm volatile(
        "mma.sync.aligned.m16n8k16.row.col.f32.f16.f16.f32 "
        "{%0,%1,%2,%3}, {%4,%5,%6,%7}, {%8,%9}, {%0,%1,%2,%3};\n"
        : "+f"(c[0]), "+f"(c[1]), "+f"(c[2]), "+f"(c[3])
        : "r"(a[0]), "r"(a[1]), "r"(a[2]), "r"(a[3]), "r"(b0), "r"(b1));
}
__device__ __forceinline__ uint32_t pack_h2(__half a, __half b) {
    __half2 h = __halves2half2(a, b);
    return *(uint32_t*)&h;
}
__device__ __forceinline__ float silu_f(float g) { return g / (1.f + __expf(-g)); }

#define CP16(d, s)  asm volatile("cp.async.cg.shared.global [%0], [%1], 16;" :: "r"(d), "l"(s))
#define CPCOMMIT()  asm volatile("cp.async.commit_group;" ::: "memory")
#define CPWAIT1()   asm volatile("cp.async.wait_group 1;" ::: "memory")

// ============================ fp32 -> fp16 conversion ============================
__global__ void cvt_kernel(const float* __restrict__ src, int which, int n8)
{
    int i = blockIdx.x*256 + threadIdx.x;
    if (i >= n8) return;
    __half* dst = (which==0) ? g_wgh : (which==1) ? g_wuh : (which==2) ? g_wdh
                : (which==3) ? g_shgh : (which==4) ? g_shuh : (which==5) ? g_shdh : g_xh;
    const float4* s4 = (const float4*)src;
    float4 a = s4[2*i], b = s4[2*i+1];
    uint4 o;
    o.x = pack_h2(__float2half_rn(a.x), __float2half_rn(a.y));
    o.y = pack_h2(__float2half_rn(a.z), __float2half_rn(a.w));
    o.z = pack_h2(__float2half_rn(b.x), __float2half_rn(b.y));
    o.w = pack_h2(__float2half_rn(b.z), __float2half_rn(b.w));
    ((uint4*)dst)[i] = o;
}

// ============================ router ============================
__global__ void router_kernel(const float* __restrict__ x,
                              const float* __restrict__ rw,
                              const float* __restrict__ seg)
{
    int t = blockIdx.x;
    int tid = threadIdx.x;              // 64 threads
    __shared__ float xs[HH];
    __shared__ float lg[EE];
    __shared__ float red[64];
    const float* xr = x + (size_t)t*HH;
    for (int i = tid; i < HH; i += 64) xs[i] = xr[i];
    __syncthreads();
    if (tid < EE) {
        float a=0.f,b=0.f,c=0.f,d=0.f;
        for (int k = 0; k < HH; k += 4) {
            a = fmaf(xs[k+0], rw[(size_t)(k+0)*EE + tid], a);
            b = fmaf(xs[k+1], rw[(size_t)(k+1)*EE + tid], b);
            c = fmaf(xs[k+2], rw[(size_t)(k+2)*EE + tid], c);
            d = fmaf(xs[k+3], rw[(size_t)(k+3)*EE + tid], d);
        }
        lg[tid] = (a+b)+(c+d);
    }
    float p = 0.f;
    for (int k = tid; k < HH; k += 64) p = fmaf(xs[k], seg[k], p);
    red[tid] = p;
    __syncthreads();
    if (tid == 0) {
        float m = lg[0];
        for (int e = 1; e < EE; e++) m = fmaxf(m, lg[e]);
        float s = 0.f;
        for (int e = 0; e < EE; e++) { float v = __expf(lg[e]-m); lg[e] = v; s += v; }
        float inv = 1.f/s;
        for (int e = 0; e < EE; e++) lg[e] *= inv;
        for (int j = 0; j < TK; j++) {
            int bi = 0; float bv = lg[0];
            for (int e = 1; e < EE; e++) { if (lg[e] > bv) { bv = lg[e]; bi = e; } }
            g_topidx[t*TK+j] = bi;
            g_topw[t*TK+j]  = bv;
            lg[bi] = -1.f;
        }
        float ss = 0.f;
        for (int i = 0; i < 64; i++) ss += red[i];
        g_sig[t] = 1.f/(1.f + __expf(-ss));
    }
}

__global__ void build1_kernel()
{
    __shared__ int cnt[EE];
    int tid = threadIdx.x;              // 256
    if (tid < EE) cnt[tid] = 0;
    __syncthreads();
    for (int p = tid; p < NP; p += 256) atomicAdd(&cnt[g_topidx[p]], 1);
    __syncthreads();
    if (tid == 0) {
        int s = 0;
        for (int e = 0; e < EE; e++) { g_off[e] = s; s += cnt[e]; }
        g_off[EE] = s;
    }
}

__global__ void build2_kernel()
{
    __shared__ int sidx[NP];            // 32 KB
    int tid = threadIdx.x;              // 256, grid 32
    for (int i = tid; i < NP; i += 256) sidx[i] = g_topidx[i];
    __syncthreads();
    int p = blockIdx.x*256 + tid;
    int e = sidx[p];
    int r = 0;
    for (int q = 0; q < p; q++) r += (sidx[q] == e);
    int pos = g_off[e] + r;
    g_tok[pos] = p >> 2;
    g_pos[p]   = pos;
}

// ============================ cp.async HMMA GEMM (BK=64, 3-stage) ============================
// CTA 128x128, BK=64, 8 warps (warp 32x64), fp16 A and B.
// Stage: A [128 rows x 144B pitch] (18432B) | B [64 rows x 272B pitch] (17408B)
#define B_OF   18432
#define STAGEB 35840
#define GSMEM  (3*STAGEB)

// MOE=false: MODE0 y16=x@shg | MODE1 y16=silu(y16)*(x@shu) | MODE2 out=sig*(y16@shd)
// MOE=true : MODE0 h16=x[tok]@wg[e] | MODE1 h16=silu(h16)*(x[tok]@wu[e]) | MODE2 pbuf=h16@wd[e]
template<int MODE, bool MOE>
__global__ void __launch_bounds__(256,2) gemm_cp(float* __restrict__ Cex)
{
    constexpr int K = MOE ? ((MODE==2) ? FF : HH) : ((MODE==2) ? SS : HH);
    constexpr int N = MOE ? ((MODE==2) ? HH : FF) : ((MODE==2) ? HH : SS);
    constexpr int NSLAB = K/64;

    extern __shared__ __align__(16) char dsm[];
    const uint32_t sb = smem_u32(dsm);

    const int tid = threadIdx.x, lane = tid & 31, w = tid >> 5;
    const int wm = (w & 3)*32, wn = (w >> 2)*64;

    int e = 0, off = 0, cnt = TT;
    if (MOE) { e = blockIdx.z; off = g_off[e]; cnt = g_off[e+1] - off; }
    const int mb = blockIdx.y*128;
    if (MOE && mb >= cnt) return;
    const int nb = blockIdx.x*128;

    const __half* Bh = MOE ? ((MODE==0) ? g_wgh : (MODE==1) ? g_wuh : g_wdh)
                           : ((MODE==0) ? g_shgh : (MODE==1) ? g_shuh : g_shdh);
    const __half* Bp = MOE ? Bh + (size_t)e*K*N : Bh;

    // ---- A fill: 1 row per 2 threads, 64B (4x16B) per thread ----
    const int ar = tid >> 1, aseg = tid & 1;
    const __half* pa;
    if (MOE) {
        int rc = (mb+ar < cnt) ? (mb+ar) : (cnt-1);
        if (MODE < 2) pa = g_xh + (size_t)g_tok[off+rc]*HH + aseg*32;
        else          pa = g_hbuf16 + (size_t)(off+rc)*FF + aseg*32;
    } else {
        const __half* Ah = (MODE==2) ? g_ybuf16 : g_xh;
        pa = Ah + (size_t)(mb+ar)*K + aseg*32;
    }
    const uint32_t dA = (uint32_t)(ar*144 + aseg*64);

    // ---- B fill: 1 row per 4 threads, 64B (4x16B) per thread ----
    const int br = tid >> 2, bseg = tid & 3;
    const __half* pb = Bp + (size_t)br*N + nb + bseg*32;
    const uint32_t dB = (uint32_t)(B_OF + br*272 + bseg*64);

    // ---- fragment addresses ----
    const int lr = lane & 15, lc = lane >> 4;
    const uint32_t aoff0 = (uint32_t)((wm + lr)*144 + lc*16);
    const uint32_t aoff1 = aoff0 + 16*144;
    uint32_t boff[4];
    #pragma unroll
    for (int np = 0; np < 4; np++)
        boff[np] = (uint32_t)(B_OF + lr*272 + (wn + np*16 + lc*8)*2);

    float acc[2][8][4] = {};

    // ---- prologue: fill stages 0,1 ----
    #pragma unroll
    for (int s = 0; s < 2; s++) {
        uint32_t base = sb + s*STAGEB;
        #pragma unroll
        for (int i = 0; i < 4; i++) CP16(base + dA + i*16, pa + (size_t)s*64 + i*8);
        #pragma unroll
        for (int i = 0; i < 4; i++) CP16(base + dB + i*16, pb + (size_t)s*64*N + i*8);
        CPCOMMIT();
    }

    for (int s = 0; s < NSLAB; s++) {
        CPWAIT1();
        __syncthreads();
        if (s + 2 < NSLAB) {
            uint32_t base = sb + (uint32_t)(((s+2) % 3)*STAGEB);
            #pragma unroll
            for (int i = 0; i < 4; i++) CP16(base + dA + i*16, pa + (size_t)(s+2)*64 + i*8);
            #pragma unroll
            for (int i = 0; i < 4; i++) CP16(base + dB + i*16, pb + (size_t)(s+2)*64*N + i*8);
        }
        CPCOMMIT();   // unconditional: keeps group count aligned in tail
        const uint32_t sbb = sb + (uint32_t)((s % 3)*STAGEB);
        #pragma unroll
        for (int ks = 0; ks < 4; ks++) {
            uint32_t a0[4], a1[4];
            ldsm4(a0, sbb + aoff0 + ks*32);
            ldsm4(a1, sbb + aoff1 + ks*32);
            #pragma unroll
            for (int np = 0; np < 4; np++) {
                uint32_t bb[4];
                ldsm4t(bb, sbb + boff[np] + ks*16*272);
                mma_f16(acc[0][2*np],   a0, bb[0], bb[1]);
                mma_f16(acc[0][2*np+1], a0, bb[2], bb[3]);
                mma_f16(acc[1][2*np],   a1, bb[0], bb[1]);
                mma_f16(acc[1][2*np+1], a1, bb[2], bb[3]);
            }
        }
    }

    // ---- epilogue ----
    #pragma unroll
    for (int mt = 0; mt < 2; mt++) {
        const int rl0 = mb + wm + mt*16 + (lane >> 2);
        const int rl1 = rl0 + 8;
        const bool v0 = MOE ? (rl0 < cnt) : true;
        const bool v1 = MOE ? (rl1 < cnt) : true;
        #pragma unroll
        for (int nt = 0; nt < 8; nt++) {
            const int col = nb + wn + nt*8 + (lane & 3)*2;
            const float* c = acc[mt][nt];
            if (!MOE) {
                if (MODE == 0) {
                    *(__half2*)&g_ybuf16[(size_t)rl0*SS + col] = __floats2half2_rn(c[0], c[1]);
                    *(__half2*)&g_ybuf16[(size_t)rl1*SS + col] = __floats2half2_rn(c[2], c[3]);
                } else if (MODE == 1) {
                    __half2 ga = *(__half2*)&g_ybuf16[(size_t)rl0*SS + col];
                    __half2 gb = *(__half2*)&g_ybuf16[(size_t)rl1*SS + col];
                    *(__half2*)&g_ybuf16[(size_t)rl0*SS + col] =
                        __floats2half2_rn(silu_f(__half2float(ga.x))*c[0],
                                          silu_f(__half2float(ga.y))*c[1]);
                    *(__half2*)&g_ybuf16[(size_t)rl1*SS + col] =
                        __floats2half2_rn(silu_f(__half2float(gb.x))*c[2],
                                          silu_f(__half2float(gb.y))*c[3]);
                } else {
                    float s0 = g_sig[rl0], s1 = g_sig[rl1];
                    *(float2*)&Cex[(size_t)rl0*HH + col] = make_float2(s0*c[0], s0*c[1]);
                    *(float2*)&Cex[(size_t)rl1*HH + col] = make_float2(s1*c[2], s1*c[3]);
                }
            } else {
                if (MODE == 0) {
                    if (v0) *(__half2*)&g_hbuf16[(size_t)(off+rl0)*FF + col] = __floats2half2_rn(c[0], c[1]);
                    if (v1) *(__half2*)&g_hbuf16[(size_t)(off+rl1)*FF + col] = __floats2half2_rn(c[2], c[3]);
                } else if (MODE == 1) {
                    if (v0) {
                        __half2 g = *(__half2*)&g_hbuf16[(size_t)(off+rl0)*FF + col];
                        *(__half2*)&g_hbuf16[(size_t)(off+rl0)*FF + col] =
                            __floats2half2_rn(silu_f(__half2float(g.x))*c[0],
                                              silu_f(__half2float(g.y))*c[1]);
                    }
                    if (v1) {
                        __half2 g = *(__half2*)&g_hbuf16[(size_t)(off+rl1)*FF + col];
                        *(__half2*)&g_hbuf16[(size_t)(off+rl1)*FF + col] =
                            __floats2half2_rn(silu_f(__half2float(g.x))*c[2],
                                              silu_f(__half2float(g.y))*c[3]);
                    }
                } else {
                    if (v0) *(float2*)&g_pbuf[(size_t)(off+rl0)*HH + col] = make_float2(c[0], c[1]);
                    if (v1) *(float2*)&g_pbuf[(size_t)(off+rl1)*HH + col] = make_float2(c[2], c[3]);
                }
            }
        }
    }
}

// ============================ combine ============================
__global__ void combine_kernel(float* __restrict__ out)
{
    int t = blockIdx.x, tid = threadIdx.x;
    int p0 = g_pos[t*4+0], p1 = g_pos[t*4+1], p2 = g_pos[t*4+2], p3 = g_pos[t*4+3];
    float w0 = g_topw[t*4+0], w1 = g_topw[t*4+1], w2 = g_topw[t*4+2], w3 = g_topw[t*4+3];
    const float* r0 = g_pbuf + (size_t)p0*HH;
    const float* r1 = g_pbuf + (size_t)p1*HH;
    const float* r2 = g_pbuf + (size_t)p2*HH;
    const float* r3 = g_pbuf + (size_t)p3*HH;
    for (int c = tid; c < HH; c += 256) {
        float v = out[(size_t)t*HH + c];
        v = fmaf(w0, r0[c], v);
        v = fmaf(w1, r1[c], v);
        v = fmaf(w2, r2[c], v);
        v = fmaf(w3, r3[c], v);
        out[(size_t)t*HH + c] = v;
    }
}

// ============================ launch ============================
extern "C" void kernel_launch(void* const* d_in, const int* in_sizes, int n_in,
                              void* d_out, int out_size)
{
    const float* x   = (const float*)d_in[0];
    const float* rw  = (const float*)d_in[1];
    const float* wg  = (const float*)d_in[2];
    const float* wu  = (const float*)d_in[3];
    const float* wd  = (const float*)d_in[4];
    const float* shg = (const float*)d_in[5];
    const float* shu = (const float*)d_in[6];
    const float* shd = (const float*)d_in[7];
    const float* seg = (const float*)d_in[8];
    float* out = (float*)d_out;
    (void)in_sizes; (void)n_in; (void)out_size;

    cudaFuncSetAttribute(gemm_cp<0,false>, cudaFuncAttributeMaxDynamicSharedMemorySize, GSMEM);
    cudaFuncSetAttribute(gemm_cp<1,false>, cudaFuncAttributeMaxDynamicSharedMemorySize, GSMEM);
    cudaFuncSetAttribute(gemm_cp<2,false>, cudaFuncAttributeMaxDynamicSharedMemorySize, GSMEM);
    cudaFuncSetAttribute(gemm_cp<0,true>,  cudaFuncAttributeMaxDynamicSharedMemorySize, GSMEM);
    cudaFuncSetAttribute(gemm_cp<1,true>,  cudaFuncAttributeMaxDynamicSharedMemorySize, GSMEM);
    cudaFuncSetAttribute(gemm_cp<2,true>,  cudaFuncAttributeMaxDynamicSharedMemorySize, GSMEM);

    // ---- fp32 -> fp16 conversions ----
    const int nW  = EE*HH*FF/8;
    const int nSH = HH*SS/8;
    const int nX  = TT*HH/8;
    cvt_kernel<<<(nW +255)/256, 256>>>(wg,  0, nW);
    cvt_kernel<<<(nW +255)/256, 256>>>(wu,  1, nW);
    cvt_kernel<<<(nW +255)/256, 256>>>(wd,  2, nW);
    cvt_kernel<<<(nSH+255)/256, 256>>>(shg, 3, nSH);
    cvt_kernel<<<(nSH+255)/256, 256>>>(shu, 4, nSH);
    cvt_kernel<<<(nSH+255)/256, 256>>>(shd, 5, nSH);
    cvt_kernel<<<(nX +255)/256, 256>>>(x,   6, nX);

    // ---- routing ----
    router_kernel<<<TT, 64>>>(x, rw, seg);
    build1_kernel<<<1, 256>>>();
    build2_kernel<<<32, 256>>>();

    // ---- shared expert ----
    gemm_cp<0,false><<<dim3(SS/128, TT/128), 256, GSMEM>>>(nullptr);
    gemm_cp<1,false><<<dim3(SS/128, TT/128), 256, GSMEM>>>(nullptr);
    gemm_cp<2,false><<<dim3(HH/128, TT/128), 256, GSMEM>>>(out);

    // ---- MoE experts ----
    gemm_cp<0,true><<<dim3(FF/128, TT/128, EE), 256, GSMEM>>>(nullptr);
    gemm_cp<1,true><<<dim3(FF/128, TT/128, EE), 256, GSMEM>>>(nullptr);
    gemm_cp<2,true><<<dim3(HH/128, TT/128, EE), 256, GSMEM>>>(nullptr);

    combine_kernel<<<TT, 256>>>(out);
}

// round 10
// speedup vs baseline: 1.5606x; 1.5606x over previous
#include <cuda_runtime.h>
#include <cuda_fp16.h>
#include <stdint.h>
#include <math.h>

#define TT 2048     // tokens
#define HH 2048     // hidden
#define FF 1408     // moe intermediate
#define EE 60       // experts
#define TK 4        // top-k
#define SS 5632     // shared intermediate
#define NP (TT*TK)  // routed pairs

// ---- fp16 operand buffers (converted once per call) ----
__device__ __align__(16) __half g_wgh[(size_t)EE*HH*FF];
__device__ __align__(16) __half g_wuh[(size_t)EE*HH*FF];
__device__ __align__(16) __half g_wdh[(size_t)EE*FF*HH];
__device__ __align__(16) __half g_shgh[(size_t)HH*SS];
__device__ __align__(16) __half g_shuh[(size_t)HH*SS];
__device__ __align__(16) __half g_shdh[(size_t)SS*HH];
__device__ __align__(16) __half g_xh[(size_t)TT*HH];
// ---- intermediates ----
__device__ __align__(16) __half g_ybuf16[(size_t)TT*SS];
__device__ __align__(16) __half g_hbuf16[(size_t)NP*FF];
__device__ float g_pbuf[(size_t)NP*HH];
// ---- routing ----
__device__ float g_topw[NP];
__device__ int   g_topidx[NP];
__device__ float g_sig[TT];
__device__ int   g_off[EE+1];
__device__ int   g_tok[NP];
__device__ int   g_pos[NP];

// ============================ helpers ============================
__device__ __forceinline__ uint32_t smem_u32(const void* p) {
    uint32_t a;
    asm("{ .reg .u64 t; cvta.to.shared.u64 t, %1; cvt.u32.u64 %0, t; }" : "=r"(a) : "l"(p));
    return a;
}
__device__ __forceinline__ void ldsm4(uint32_t r[4], uint32_t addr) {
    asm volatile("ldmatrix.sync.aligned.m8n8.x4.shared.b16 {%0,%1,%2,%3}, [%4];"
        : "=r"(r[0]), "=r"(r[1]), "=r"(r[2]), "=r"(r[3]) : "r"(addr));
}
__device__ __forceinline__ void ldsm4t(uint32_t r[4], uint32_t addr) {
    asm volatile("ldmatrix.sync.aligned.m8n8.x4.trans.shared.b16 {%0,%1,%2,%3}, [%4];"
        : "=r"(r[0]), "=r"(r[1]), "=r"(r[2]), "=r"(r[3]) : "r"(addr));
}
__device__ __forceinline__ void mma_f16(float c[4], const uint32_t a[4], uint32_t b0, uint32_t b1) {
    asm volatile(
        "mma.sync.aligned.m16n8k16.row.col.f32.f16.f16.f32 "
        "{%0,%1,%2,%3}, {%4,%5,%6,%7}, {%8,%9}, {%0,%1,%2,%3};\n"
        : "+f"(c[0]), "+f"(c[1]), "+f"(c[2]), "+f"(c[3])
        : "r"(a[0]), "r"(a[1]), "r"(a[2]), "r"(a[3]), "r"(b0), "r"(b1));
}
__device__ __forceinline__ uint32_t pack_h2(__half a, __half b) {
    __half2 h = __halves2half2(a, b);
    return *(uint32_t*)&h;
}
__device__ __forceinline__ float silu_f(float g) { return g / (1.f + __expf(-g)); }

#define CP16(d, s)  asm volatile("cp.async.cg.shared.global [%0], [%1], 16;" :: "r"(d), "l"(s))
#define CPCOMMIT()  asm volatile("cp.async.commit_group;" ::: "memory")
#define CPWAIT2()   asm volatile("cp.async.wait_group 2;" ::: "memory")

// ============================ fp32 -> fp16 conversion ============================
__global__ void cvt_kernel(const float* __restrict__ src, int which, int n8)
{
    int i = blockIdx.x*256 + threadIdx.x;
    if (i >= n8) return;
    __half* dst = (which==0) ? g_wgh : (which==1) ? g_wuh : (which==2) ? g_wdh
                : (which==3) ? g_shgh : (which==4) ? g_shuh : (which==5) ? g_shdh : g_xh;
    const float4* s4 = (const float4*)src;
    float4 a = s4[2*i], b = s4[2*i+1];
    uint4 o;
    o.x = pack_h2(__float2half_rn(a.x), __float2half_rn(a.y));
    o.y = pack_h2(__float2half_rn(a.z), __float2half_rn(a.w));
    o.z = pack_h2(__float2half_rn(b.x), __float2half_rn(b.y));
    o.w = pack_h2(__float2half_rn(b.z), __float2half_rn(b.w));
    ((uint4*)dst)[i] = o;
}

// ============================ router ============================
__global__ void router_kernel(const float* __restrict__ x,
                              const float* __restrict__ rw,
                              const float* __restrict__ seg)
{
    int t = blockIdx.x;
    int tid = threadIdx.x;              // 64 threads
    __shared__ float xs[HH];
    __shared__ float lg[EE];
    __shared__ float red[64];
    const float* xr = x + (size_t)t*HH;
    for (int i = tid; i < HH; i += 64) xs[i] = xr[i];
    __syncthreads();
    if (tid < EE) {
        float a=0.f,b=0.f,c=0.f,d=0.f;
        for (int k = 0; k < HH; k += 4) {
            a = fmaf(xs[k+0], rw[(size_t)(k+0)*EE + tid], a);
            b = fmaf(xs[k+1], rw[(size_t)(k+1)*EE + tid], b);
            c = fmaf(xs[k+2], rw[(size_t)(k+2)*EE + tid], c);
            d = fmaf(xs[k+3], rw[(size_t)(k+3)*EE + tid], d);
        }
        lg[tid] = (a+b)+(c+d);
    }
    float p = 0.f;
    for (int k = tid; k < HH; k += 64) p = fmaf(xs[k], seg[k], p);
    red[tid] = p;
    __syncthreads();
    if (tid == 0) {
        float m = lg[0];
        for (int e = 1; e < EE; e++) m = fmaxf(m, lg[e]);
        float s = 0.f;
        for (int e = 0; e < EE; e++) { float v = __expf(lg[e]-m); lg[e] = v; s += v; }
        float inv = 1.f/s;
        for (int e = 0; e < EE; e++) lg[e] *= inv;
        for (int j = 0; j < TK; j++) {
            int bi = 0; float bv = lg[0];
            for (int e = 1; e < EE; e++) { if (lg[e] > bv) { bv = lg[e]; bi = e; } }
            g_topidx[t*TK+j] = bi;
            g_topw[t*TK+j]  = bv;
            lg[bi] = -1.f;
        }
        float ss = 0.f;
        for (int i = 0; i < 64; i++) ss += red[i];
        g_sig[t] = 1.f/(1.f + __expf(-ss));
    }
}

__global__ void build1_kernel()
{
    __shared__ int cnt[EE];
    int tid = threadIdx.x;              // 256
    if (tid < EE) cnt[tid] = 0;
    __syncthreads();
    for (int p = tid; p < NP; p += 256) atomicAdd(&cnt[g_topidx[p]], 1);
    __syncthreads();
    if (tid == 0) {
        int s = 0;
        for (int e = 0; e < EE; e++) { g_off[e] = s; s += cnt[e]; }
        g_off[EE] = s;
    }
}

__global__ void build2_kernel()
{
    __shared__ int sidx[NP];            // 32 KB
    int tid = threadIdx.x;              // 256, grid 32
    for (int i = tid; i < NP; i += 256) sidx[i] = g_topidx[i];
    __syncthreads();
    int p = blockIdx.x*256 + tid;
    int e = sidx[p];
    int r = 0;
    for (int q = 0; q < p; q++) r += (sidx[q] == e);
    int pos = g_off[e] + r;
    g_tok[pos] = p >> 2;
    g_pos[p]   = pos;
}

// ============================ shared pipeline constants (R8 config) ============================
// Stage: A [128 rows x 80B pitch] (10240B) | B [32 rows x 272B pitch] (8704B)
#define STAGEB 18944
#define B_OF   10240
#define GSMEM  (4*STAGEB)

// ============================ fused gate+up GEMM ============================
// CTA: 128 rows x 64 output cols. Staged B panel: gate cols [0,64) | up cols [64,128).
// Epilogue: out16 = silu(gate) * up  (single write, no roundtrip).
// MOE=false: ybuf16[mb..][nb..] ; MOE=true: hbuf16 rows off+rl (guarded)
template<bool MOE>
__global__ void __launch_bounds__(256,2) gemm_gateup(int dummy)
{
    constexpr int K = HH;
    constexpr int N = MOE ? FF : SS;
    constexpr int NSLAB = K/32;

    extern __shared__ __align__(16) char dsm[];
    const uint32_t sb = smem_u32(dsm);

    const int tid = threadIdx.x, lane = tid & 31, w = tid >> 5;
    const int wm = (w & 3)*32, wn2 = (w >> 2)*32;   // warp: 32 rows x 32 cols (x2 matrices)

    int e = 0, off = 0, cnt = TT;
    if (MOE) { e = blockIdx.z; off = g_off[e]; cnt = g_off[e+1] - off; }
    const int mb = blockIdx.y*128;
    if (MOE && mb >= cnt) return;
    const int nb = blockIdx.x*64;

    const __half* Bg = MOE ? g_wgh + (size_t)e*K*N : g_shgh;
    const __half* Bu = MOE ? g_wuh + (size_t)e*K*N : g_shuh;

    // ---- A fill (2 cp16/thread) ----
    const int aseg = tid & 3, ar0 = tid >> 2, ar1 = (tid >> 2) + 64;
    const __half *pa0, *pa1;
    if (MOE) {
        int rc0 = (mb+ar0 < cnt) ? (mb+ar0) : (cnt-1);
        int rc1 = (mb+ar1 < cnt) ? (mb+ar1) : (cnt-1);
        pa0 = g_xh + (size_t)g_tok[off+rc0]*HH + aseg*8;
        pa1 = g_xh + (size_t)g_tok[off+rc1]*HH + aseg*8;
    } else {
        pa0 = g_xh + (size_t)(mb+ar0)*K + aseg*8;
        pa1 = g_xh + (size_t)(mb+ar1)*K + aseg*8;
    }
    const uint32_t dA0 = (uint32_t)(ar0*80 + aseg*16);
    const uint32_t dA1 = (uint32_t)(ar1*80 + aseg*16);

    // ---- B fill (2 cp16/thread): segs 0-7 gate cols, 8-15 up cols ----
    const int br = tid >> 4, bseg = tid & 15;
    const int cseg = bseg & 7;
    const __half* bsrc = ((bseg & 8) ? Bu : Bg) + (size_t)br*N + nb + cseg*8;
    const uint32_t dB0 = (uint32_t)(B_OF + br*272 + bseg*16);
    const uint32_t dB1 = dB0 + 16*272;
    const __half* pb0 = bsrc;
    const __half* pb1 = bsrc + (size_t)16*N;

    // ---- fragment addresses ----
    const int lr = lane & 15, lc = lane >> 4;
    const uint32_t aoff0 = (uint32_t)((wm + lr)*80 + lc*16);
    const uint32_t aoff1 = aoff0 + 16*80;
    uint32_t bG[2], bU[2];
    #pragma unroll
    for (int np = 0; np < 2; np++) {
        bG[np] = (uint32_t)(B_OF + lr*272 + (wn2 + np*16 + lc*8)*2);
        bU[np] = bG[np] + 128;     // +64 cols
    }

    float accG[2][4][4] = {}, accU[2][4][4] = {};

    // ---- prologue: stages 0..2 ----
    #pragma unroll
    for (int s = 0; s < 3; s++) {
        uint32_t base = sb + s*STAGEB;
        CP16(base + dA0, pa0 + s*32);
        CP16(base + dA1, pa1 + s*32);
        CP16(base + dB0, pb0 + (size_t)s*32*N);
        CP16(base + dB1, pb1 + (size_t)s*32*N);
        CPCOMMIT();
    }

    for (int s = 0; s < NSLAB; s++) {
        CPWAIT2();
        __syncthreads();
        if (s + 3 < NSLAB) {
            uint32_t base = sb + ((s+3) & 3)*STAGEB;
            CP16(base + dA0, pa0 + (s+3)*32);
            CP16(base + dA1, pa1 + (s+3)*32);
            CP16(base + dB0, pb0 + (size_t)(s+3)*32*N);
            CP16(base + dB1, pb1 + (size_t)(s+3)*32*N);
        }
        CPCOMMIT();
        const uint32_t sbb = sb + (uint32_t)((s & 3)*STAGEB);
        #pragma unroll
        for (int ks = 0; ks < 2; ks++) {
            uint32_t a0[4], a1[4];
            ldsm4(a0, sbb + aoff0 + ks*32);
            ldsm4(a1, sbb + aoff1 + ks*32);
            #pragma unroll
            for (int np = 0; np < 2; np++) {
                uint32_t gg[4], uu[4];
                ldsm4t(gg, sbb + bG[np] + ks*16*272);
                ldsm4t(uu, sbb + bU[np] + ks*16*272);
                mma_f16(accG[0][2*np],   a0, gg[0], gg[1]);
                mma_f16(accG[0][2*np+1], a0, gg[2], gg[3]);
                mma_f16(accG[1][2*np],   a1, gg[0], gg[1]);
                mma_f16(accG[1][2*np+1], a1, gg[2], gg[3]);
                mma_f16(accU[0][2*np],   a0, uu[0], uu[1]);
                mma_f16(accU[0][2*np+1], a0, uu[2], uu[3]);
                mma_f16(accU[1][2*np],   a1, uu[0], uu[1]);
                mma_f16(accU[1][2*np+1], a1, uu[2], uu[3]);
            }
        }
    }

    // ---- epilogue: h = silu(gate) * up, single fp16 write ----
    __half* dst = MOE ? g_hbuf16 : g_ybuf16;
    #pragma unroll
    for (int mt = 0; mt < 2; mt++) {
        const int rl0 = mb + wm + mt*16 + (lane >> 2);
        const int rl1 = rl0 + 8;
        const bool v0 = MOE ? (rl0 < cnt) : true;
        const bool v1 = MOE ? (rl1 < cnt) : true;
        const size_t row0 = MOE ? (size_t)(off + rl0) : (size_t)rl0;
        const size_t row1 = MOE ? (size_t)(off + rl1) : (size_t)rl1;
        #pragma unroll
        for (int nt = 0; nt < 4; nt++) {
            const int col = nb + wn2 + nt*8 + (lane & 3)*2;
            const float* g = accG[mt][nt];
            const float* u = accU[mt][nt];
            if (v0) *(__half2*)&dst[row0*N + col] =
                __floats2half2_rn(silu_f(g[0])*u[0], silu_f(g[1])*u[1]);
            if (v1) *(__half2*)&dst[row1*N + col] =
                __floats2half2_rn(silu_f(g[2])*u[2], silu_f(g[3])*u[3]);
        }
    }
}

// ============================ down GEMM (R8 config) ============================
// MOE=false: out = sig * (ybuf16 @ shd)  ; MOE=true: pbuf = hbuf16 @ wd[e]
template<bool MOE>
__global__ void __launch_bounds__(256,2) gemm_down(float* __restrict__ Cex)
{
    constexpr int K = MOE ? FF : SS;
    constexpr int N = HH;
    constexpr int NSLAB = K/32;

    extern __shared__ __align__(16) char dsm[];
    const uint32_t sb = smem_u32(dsm);

    const int tid = threadIdx.x, lane = tid & 31, w = tid >> 5;
    const int wm = (w & 3)*32, wn = (w >> 2)*64;

    int e = 0, off = 0, cnt = TT;
    if (MOE) { e = blockIdx.z; off = g_off[e]; cnt = g_off[e+1] - off; }
    const int mb = blockIdx.y*128;
    if (MOE && mb >= cnt) return;
    const int nb = blockIdx.x*128;

    const __half* Bp = MOE ? g_wdh + (size_t)e*K*N : g_shdh;

    // ---- A fill ----
    const int aseg = tid & 3, ar0 = tid >> 2, ar1 = (tid >> 2) + 64;
    const __half *pa0, *pa1;
    if (MOE) {
        int rc0 = (mb+ar0 < cnt) ? (mb+ar0) : (cnt-1);
        int rc1 = (mb+ar1 < cnt) ? (mb+ar1) : (cnt-1);
        pa0 = g_hbuf16 + (size_t)(off+rc0)*FF + aseg*8;
        pa1 = g_hbuf16 + (size_t)(off+rc1)*FF + aseg*8;
    } else {
        pa0 = g_ybuf16 + (size_t)(mb+ar0)*K + aseg*8;
        pa1 = g_ybuf16 + (size_t)(mb+ar1)*K + aseg*8;
    }
    const uint32_t dA0 = (uint32_t)(ar0*80 + aseg*16);
    const uint32_t dA1 = (uint32_t)(ar1*80 + aseg*16);

    // ---- B fill ----
    const int bseg = tid & 15, br0 = tid >> 4, br1 = (tid >> 4) + 16;
    const __half* pb0 = Bp + (size_t)br0*N + nb + bseg*8;
    const __half* pb1 = Bp + (size_t)br1*N + nb + bseg*8;
    const uint32_t dB0 = (uint32_t)(B_OF + br0*272 + bseg*16);
    const uint32_t dB1 = (uint32_t)(B_OF + br1*272 + bseg*16);

    // ---- fragment addresses ----
    const int lr = lane & 15, lc = lane >> 4;
    const uint32_t aoff0 = (uint32_t)((wm + lr)*80 + lc*16);
    const uint32_t aoff1 = aoff0 + 16*80;
    uint32_t boff[4];
    #pragma unroll
    for (int np = 0; np < 4; np++)
        boff[np] = (uint32_t)(B_OF + lr*272 + (wn + np*16 + lc*8)*2);

    float acc[2][8][4] = {};

    #pragma unroll
    for (int s = 0; s < 3; s++) {
        uint32_t base = sb + s*STAGEB;
        CP16(base + dA0, pa0 + s*32);
        CP16(base + dA1, pa1 + s*32);
        CP16(base + dB0, pb0 + (size_t)s*32*N);
        CP16(base + dB1, pb1 + (size_t)s*32*N);
        CPCOMMIT();
    }

    for (int s = 0; s < NSLAB; s++) {
        CPWAIT2();
        __syncthreads();
        if (s + 3 < NSLAB) {
            uint32_t base = sb + ((s+3) & 3)*STAGEB;
            CP16(base + dA0, pa0 + (s+3)*32);
            CP16(base + dA1, pa1 + (s+3)*32);
            CP16(base + dB0, pb0 + (size_t)(s+3)*32*N);
            CP16(base + dB1, pb1 + (size_t)(s+3)*32*N);
        }
        CPCOMMIT();
        const uint32_t sbb = sb + (uint32_t)((s & 3)*STAGEB);
        #pragma unroll
        for (int ks = 0; ks < 2; ks++) {
            uint32_t a0[4], a1[4];
            ldsm4(a0, sbb + aoff0 + ks*32);
            ldsm4(a1, sbb + aoff1 + ks*32);
            #pragma unroll
            for (int np = 0; np < 4; np++) {
                uint32_t bb[4];
                ldsm4t(bb, sbb + boff[np] + ks*16*272);
                mma_f16(acc[0][2*np],   a0, bb[0], bb[1]);
                mma_f16(acc[0][2*np+1], a0, bb[2], bb[3]);
                mma_f16(acc[1][2*np],   a1, bb[0], bb[1]);
                mma_f16(acc[1][2*np+1], a1, bb[2], bb[3]);
            }
        }
    }

    // ---- epilogue ----
    #pragma unroll
    for (int mt = 0; mt < 2; mt++) {
        const int rl0 = mb + wm + mt*16 + (lane >> 2);
        const int rl1 = rl0 + 8;
        const bool v0 = MOE ? (rl0 < cnt) : true;
        const bool v1 = MOE ? (rl1 < cnt) : true;
        #pragma unroll
        for (int nt = 0; nt < 8; nt++) {
            const int col = nb + wn + nt*8 + (lane & 3)*2;
            const float* c = acc[mt][nt];
            if (!MOE) {
                float s0 = g_sig[rl0], s1 = g_sig[rl1];
                *(float2*)&Cex[(size_t)rl0*HH + col] = make_float2(s0*c[0], s0*c[1]);
                *(float2*)&Cex[(size_t)rl1*HH + col] = make_float2(s1*c[2], s1*c[3]);
            } else {
                if (v0) *(float2*)&g_pbuf[(size_t)(off+rl0)*HH + col] = make_float2(c[0], c[1]);
                if (v1) *(float2*)&g_pbuf[(size_t)(off+rl1)*HH + col] = make_float2(c[2], c[3]);
            }
        }
    }
}

// ============================ combine ============================
__global__ void combine_kernel(float* __restrict__ out)
{
    int t = blockIdx.x, tid = threadIdx.x;
    int p0 = g_pos[t*4+0], p1 = g_pos[t*4+1], p2 = g_pos[t*4+2], p3 = g_pos[t*4+3];
    float w0 = g_topw[t*4+0], w1 = g_topw[t*4+1], w2 = g_topw[t*4+2], w3 = g_topw[t*4+3];
    const float* r0 = g_pbuf + (size_t)p0*HH;
    const float* r1 = g_pbuf + (size_t)p1*HH;
    const float* r2 = g_pbuf + (size_t)p2*HH;
    const float* r3 = g_pbuf + (size_t)p3*HH;
    for (int c = tid; c < HH; c += 256) {
        float v = out[(size_t)t*HH + c];
        v = fmaf(w0, r0[c], v);
        v = fmaf(w1, r1[c], v);
        v = fmaf(w2, r2[c], v);
        v = fmaf(w3, r3[c], v);
        out[(size_t)t*HH + c] = v;
    }
}

// ============================ launch ============================
extern "C" void kernel_launch(void* const* d_in, const int* in_sizes, int n_in,
                              void* d_out, int out_size)
{
    const float* x   = (const float*)d_in[0];
    const float* rw  = (const float*)d_in[1];
    const float* wg  = (const float*)d_in[2];
    const float* wu  = (const float*)d_in[3];
    const float* wd  = (const float*)d_in[4];
    const float* shg = (const float*)d_in[5];
    const float* shu = (const float*)d_in[6];
    const float* shd = (const float*)d_in[7];
    const float* seg = (const float*)d_in[8];
    float* out = (float*)d_out;
    (void)in_sizes; (void)n_in; (void)out_size;

    cudaFuncSetAttribute(gemm_gateup<false>, cudaFuncAttributeMaxDynamicSharedMemorySize, GSMEM);
    cudaFuncSetAttribute(gemm_gateup<true>,  cudaFuncAttributeMaxDynamicSharedMemorySize, GSMEM);
    cudaFuncSetAttribute(gemm_down<false>,   cudaFuncAttributeMaxDynamicSharedMemorySize, GSMEM);
    cudaFuncSetAttribute(gemm_down<true>,    cudaFuncAttributeMaxDynamicSharedMemorySize, GSMEM);

    // ---- fp32 -> fp16 conversions ----
    const int nW  = EE*HH*FF/8;
    const int nSH = HH*SS/8;
    const int nX  = TT*HH/8;
    cvt_kernel<<<(nW +255)/256, 256>>>(wg,  0, nW);
    cvt_kernel<<<(nW +255)/256, 256>>>(wu,  1, nW);
    cvt_kernel<<<(nW +255)/256, 256>>>(wd,  2, nW);
    cvt_kernel<<<(nSH+255)/256, 256>>>(shg, 3, nSH);
    cvt_kernel<<<(nSH+255)/256, 256>>>(shu, 4, nSH);
    cvt_kernel<<<(nSH+255)/256, 256>>>(shd, 5, nSH);
    cvt_kernel<<<(nX +255)/256, 256>>>(x,   6, nX);

    // ---- routing ----
    router_kernel<<<TT, 64>>>(x, rw, seg);
    build1_kernel<<<1, 256>>>();
    build2_kernel<<<32, 256>>>();

    // ---- shared expert: fused gate+up, then down ----
    gemm_gateup<false><<<dim3(SS/64, TT/128), 256, GSMEM>>>(0);
    gemm_down<false><<<dim3(HH/128, TT/128), 256, GSMEM>>>(out);

    // ---- MoE experts: fused gate+up, then down ----
    gemm_gateup<true><<<dim3(FF/64, TT/128, EE), 256, GSMEM>>>(0);
    gemm_down<true><<<dim3(HH/128, TT/128, EE), 256, GSMEM>>>(nullptr);

    combine_kernel<<<TT, 256>>>(out);
}